// round 3
// baseline (speedup 1.0000x reference)
#include <cuda_runtime.h>
#include <math.h>

// Problem constants (fixed by the dataset)
#define T_TOK 4096
#define H_DIM 1024
#define E_NUM 8
#define I_DIM 1024
#define K_TOP 2
#define NSLOT (T_TOK * K_TOP)   // 8192 (token,expert) assignments, always exactly this many

// ---------------- device scratch (static globals; no allocation allowed) ------------
__device__ int   d_counts[E_NUM];
__device__ int   d_off[E_NUM + 1];
__device__ int   d_pos[E_NUM];
__device__ int   d_a_tok[NSLOT];          // slot -> token id (expert-sorted)
__device__ float d_w[NSLOT];              // (t,k) -> combine weight
__device__ int   d_slot[NSLOT];           // (t,k) -> slot index
__device__ float d_gu[(size_t)NSLOT * 2 * I_DIM];  // 67 MB: g|u pre-activation
__device__ float d_h[(size_t)NSLOT * I_DIM];       // 33.5 MB: gelu(g)*u
__device__ float d_y[(size_t)NSLOT * H_DIM];       // 33.5 MB: per-slot down-proj

// ---------------- small kernels ----------------
__global__ void init_kernel() {
    int i = threadIdx.x;
    if (i < E_NUM) d_counts[i] = 0;
}

__global__ void router_kernel(const float* __restrict__ logits,
                              const float* __restrict__ scale) {
    int t = blockIdx.x * blockDim.x + threadIdx.x;
    if (t >= T_TOK) return;
    float l[E_NUM];
#pragma unroll
    for (int e = 0; e < E_NUM; e++) l[e] = logits[t * E_NUM + e];
    // top-1 (first occurrence on ties, matching jax top_k)
    int e0 = 0; float v0 = l[0];
#pragma unroll
    for (int e = 1; e < E_NUM; e++) if (l[e] > v0) { v0 = l[e]; e0 = e; }
    int e1 = -1; float v1 = -3.0e38f;
#pragma unroll
    for (int e = 0; e < E_NUM; e++) if (e != e0 && l[e] > v1) { v1 = l[e]; e1 = e; }
    // softmax denominator cancels in dispatch = gate / renorm
    float p0 = 1.0f;                 // exp(v0 - v0)
    float p1 = expf(v1 - v0);
    float inv = 1.0f / (p0 + p1);
    d_w[t * 2 + 0] = p0 * inv * scale[e0];
    d_w[t * 2 + 1] = p1 * inv * scale[e1];
    // stash expert ids temporarily in d_slot (overwritten by scatter)
    d_slot[t * 2 + 0] = e0;
    d_slot[t * 2 + 1] = e1;
    atomicAdd(&d_counts[e0], 1);
    atomicAdd(&d_counts[e1], 1);
}

__global__ void scan_kernel() {
    if (threadIdx.x == 0) {
        int acc = 0;
        for (int e = 0; e < E_NUM; e++) {
            d_off[e] = acc;
            d_pos[e] = acc;
            acc += d_counts[e];
        }
        d_off[E_NUM] = acc;   // == NSLOT
    }
}

__global__ void scatter_kernel() {
    int t = blockIdx.x * blockDim.x + threadIdx.x;
    if (t >= T_TOK) return;
#pragma unroll
    for (int k = 0; k < K_TOP; k++) {
        int e = d_slot[t * 2 + k];          // expert id stashed by router
        int p = atomicAdd(&d_pos[e], 1);
        d_a_tok[p] = t;
        d_slot[t * 2 + k] = p;              // now the real slot index
    }
}

// ---------------- grouped SGEMM ----------------
// MODE 0: C = d_gu[slot, n] = sum_h x[tok, h] * w13[e, n, h]      (N over 2*I)
// MODE 1: C = d_y[slot, n]  = sum_i d_h[slot, i] * w2[e, n, i]    (N over H)
// Both are A[M,K] row-major times B[N,K] row-major (C = A * B^T), K = 1024.
template <int MODE>
__global__ __launch_bounds__(256, 2)
void gemm_kernel(const float* __restrict__ X, const float* __restrict__ W) {
    const int KD = 1024;
    const int BROWS = (MODE == 0) ? (2 * I_DIM) : H_DIM;   // B rows per expert
    const int CSTR  = (MODE == 0) ? (2 * I_DIM) : H_DIM;   // C row stride

    int e = blockIdx.z;
    int m_begin = d_off[e];
    int m_count = d_off[e + 1] - m_begin;
    int tile_m = blockIdx.y * 128;
    if (tile_m >= m_count) return;
    int n0 = blockIdx.x * 128;

    __shared__ float As[16][128];
    __shared__ float Bs[16][128];

    int tid = threadIdx.x;
    int lrow = tid >> 2;          // 0..63
    int lk4  = (tid & 3) * 4;     // 0,4,8,12

    const float* arow[2];
    bool avalid[2];
#pragma unroll
    for (int i = 0; i < 2; i++) {
        int r = lrow + i * 64;
        bool v = (tile_m + r) < m_count;
        avalid[i] = v;
        int slot = m_begin + tile_m + (v ? r : 0);
        if (MODE == 0) {
            int tok = v ? d_a_tok[slot] : 0;
            arow[i] = X + (size_t)tok * KD;
        } else {
            arow[i] = d_h + (size_t)slot * KD;
        }
    }
    const float* brow[2];
#pragma unroll
    for (int i = 0; i < 2; i++) {
        int r = lrow + i * 64;
        brow[i] = W + ((size_t)e * BROWS + (n0 + r)) * KD;
    }

    float acc[8][8];
#pragma unroll
    for (int i = 0; i < 8; i++)
#pragma unroll
        for (int j = 0; j < 8; j++) acc[i][j] = 0.0f;

    int trow = (tid >> 4) * 8;
    int tcol = (tid & 15) * 8;

    for (int k0 = 0; k0 < KD; k0 += 16) {
#pragma unroll
        for (int i = 0; i < 2; i++) {
            int r = lrow + i * 64;
            float4 va = avalid[i] ? *(const float4*)(arow[i] + k0 + lk4)
                                  : make_float4(0.f, 0.f, 0.f, 0.f);
            As[lk4 + 0][r] = va.x;
            As[lk4 + 1][r] = va.y;
            As[lk4 + 2][r] = va.z;
            As[lk4 + 3][r] = va.w;
            float4 vb = *(const float4*)(brow[i] + k0 + lk4);
            Bs[lk4 + 0][r] = vb.x;
            Bs[lk4 + 1][r] = vb.y;
            Bs[lk4 + 2][r] = vb.z;
            Bs[lk4 + 3][r] = vb.w;
        }
        __syncthreads();
#pragma unroll
        for (int kk = 0; kk < 16; kk++) {
            float a[8], b[8];
            float4 a0 = *(const float4*)&As[kk][trow];
            float4 a1 = *(const float4*)&As[kk][trow + 4];
            a[0]=a0.x; a[1]=a0.y; a[2]=a0.z; a[3]=a0.w;
            a[4]=a1.x; a[5]=a1.y; a[6]=a1.z; a[7]=a1.w;
            float4 b0 = *(const float4*)&Bs[kk][tcol];
            float4 b1 = *(const float4*)&Bs[kk][tcol + 4];
            b[0]=b0.x; b[1]=b0.y; b[2]=b0.z; b[3]=b0.w;
            b[4]=b1.x; b[5]=b1.y; b[6]=b1.z; b[7]=b1.w;
#pragma unroll
            for (int i = 0; i < 8; i++)
#pragma unroll
                for (int j = 0; j < 8; j++) acc[i][j] += a[i] * b[j];
        }
        __syncthreads();
    }

    float* Cbase = (MODE == 0) ? d_gu : d_y;
#pragma unroll
    for (int i = 0; i < 8; i++) {
        int r = trow + i;
        if (tile_m + r < m_count) {
            float* crow = Cbase + (size_t)(m_begin + tile_m + r) * CSTR + n0 + tcol;
            *(float4*)(crow)     = make_float4(acc[i][0], acc[i][1], acc[i][2], acc[i][3]);
            *(float4*)(crow + 4) = make_float4(acc[i][4], acc[i][5], acc[i][6], acc[i][7]);
        }
    }
}

// ---------------- activation: h = gelu(g) * u (exact erf gelu) ----------------
__global__ void act_kernel() {
    size_t idx = (size_t)blockIdx.x * blockDim.x + threadIdx.x;
    size_t total = (size_t)NSLOT * I_DIM;
    if (idx >= total) return;
    size_t slot = idx / I_DIM;
    size_t i = idx - slot * I_DIM;
    float g = d_gu[slot * (2 * I_DIM) + i];
    float u = d_gu[slot * (2 * I_DIM) + I_DIM + i];
    float gelu = 0.5f * g * (1.0f + erff(g * 0.70710678118654752f));
    d_h[slot * I_DIM + i] = gelu * u;
}

// ---------------- combine: out[t,:] = w0*y[slot0,:] + w1*y[slot1,:] ----------------
__global__ void combine_kernel(float* __restrict__ out) {
    int idx = blockIdx.x * blockDim.x + threadIdx.x;   // over T*H/4
    int nvec = T_TOK * H_DIM / 4;
    if (idx >= nvec) return;
    int vecs_per_row = H_DIM / 4;
    int t = idx / vecs_per_row;
    int c = (idx - t * vecs_per_row) * 4;
    float w0 = d_w[t * 2 + 0];
    float w1 = d_w[t * 2 + 1];
    int s0 = d_slot[t * 2 + 0];
    int s1 = d_slot[t * 2 + 1];
    float4 y0 = *(const float4*)(d_y + (size_t)s0 * H_DIM + c);
    float4 y1 = *(const float4*)(d_y + (size_t)s1 * H_DIM + c);
    float4 o;
    o.x = w0 * y0.x + w1 * y1.x;
    o.y = w0 * y0.y + w1 * y1.y;
    o.z = w0 * y0.z + w1 * y1.z;
    o.w = w0 * y0.w + w1 * y1.w;
    *(float4*)(out + (size_t)t * H_DIM + c) = o;
}

// ---------------- launch ----------------
extern "C" void kernel_launch(void* const* d_in, const int* in_sizes, int n_in,
                              void* d_out, int out_size) {
    const float* x      = (const float*)d_in[0];
    const float* logits = (const float*)d_in[1];
    const float* scale  = (const float*)d_in[2];
    const float* w13    = (const float*)d_in[3];
    const float* w2     = (const float*)d_in[4];
    float* out = (float*)d_out;

    init_kernel<<<1, 32>>>();
    router_kernel<<<T_TOK / 256, 256>>>(logits, scale);
    scan_kernel<<<1, 32>>>();
    scatter_kernel<<<T_TOK / 256, 256>>>();

    // GEMM1: N = 2*I = 2048 -> 16 n-tiles; up to 4096 rows/expert -> 32 m-tiles
    gemm_kernel<0><<<dim3(16, 32, E_NUM), 256>>>(x, w13);

    {
        size_t total = (size_t)NSLOT * I_DIM;
        int threads = 256;
        int blocks = (int)((total + threads - 1) / threads);
        act_kernel<<<blocks, threads>>>();
    }

    // GEMM2: N = H = 1024 -> 8 n-tiles
    gemm_kernel<1><<<dim3(8, 32, E_NUM), 256>>>(nullptr, w2);

    {
        int nvec = T_TOK * H_DIM / 4;
        combine_kernel<<<(nvec + 255) / 256, 256>>>(out);
    }
}

// round 7
// speedup vs baseline: 2.2754x; 2.2754x over previous
#include <cuda_runtime.h>
#include <cuda_bf16.h>
#include <cstdint>
#include <math.h>

// Problem constants (fixed by the dataset)
#define T_TOK 4096
#define H_DIM 1024
#define E_NUM 8
#define I_DIM 1024
#define K_TOP 2
#define NSLOT (T_TOK * K_TOP)   // 8192 (token,expert) assignments

// ---------------- device scratch ----------------
__device__ int   d_counts[E_NUM];
__device__ int   d_off[E_NUM + 1];
__device__ int   d_pos[E_NUM];
__device__ int   d_a_tok[NSLOT];
__device__ float d_w[NSLOT];
__device__ int   d_slot[NSLOT];
__device__ float d_gu[(size_t)NSLOT * 2 * I_DIM];      // g|u pre-activation (fp32)
__device__ float d_y[(size_t)NSLOT * H_DIM];           // down-proj per slot (fp32)

// bf16 hi/lo split operands
__device__ __nv_bfloat16 d_x_hi[(size_t)T_TOK * H_DIM];
__device__ __nv_bfloat16 d_x_lo[(size_t)T_TOK * H_DIM];
__device__ __nv_bfloat16 d_w13_hi[(size_t)E_NUM * 2 * I_DIM * H_DIM];
__device__ __nv_bfloat16 d_w13_lo[(size_t)E_NUM * 2 * I_DIM * H_DIM];
__device__ __nv_bfloat16 d_w2_hi[(size_t)E_NUM * H_DIM * I_DIM];
__device__ __nv_bfloat16 d_w2_lo[(size_t)E_NUM * H_DIM * I_DIM];
__device__ __nv_bfloat16 d_h_hi[(size_t)NSLOT * I_DIM];
__device__ __nv_bfloat16 d_h_lo[(size_t)NSLOT * I_DIM];

// ---------------- PTX helpers ----------------
__device__ __forceinline__ uint32_t smem_u32(const void* p) {
    uint32_t a;
    asm("{ .reg .u64 t; cvta.to.shared.u64 t, %1; cvt.u32.u64 %0, t; }" : "=r"(a) : "l"(p));
    return a;
}
#define CP_ASYNC8(dst_u32, src_ptr) \
    asm volatile("cp.async.ca.shared.global [%0], [%1], 8;" :: "r"(dst_u32), "l"(src_ptr))
#define CP_COMMIT() asm volatile("cp.async.commit_group;" ::: "memory")
#define CP_WAIT1()  asm volatile("cp.async.wait_group 1;" ::: "memory")
#define CP_WAIT0()  asm volatile("cp.async.wait_group 0;" ::: "memory")

__device__ __forceinline__ void mma_bf16(float* d, const uint32_t* a, const uint32_t* b) {
    asm volatile(
        "mma.sync.aligned.m16n8k16.row.col.f32.bf16.bf16.f32 "
        "{%0,%1,%2,%3}, {%4,%5,%6,%7}, {%8,%9}, {%0,%1,%2,%3};"
        : "+f"(d[0]), "+f"(d[1]), "+f"(d[2]), "+f"(d[3])
        : "r"(a[0]), "r"(a[1]), "r"(a[2]), "r"(a[3]), "r"(b[0]), "r"(b[1]));
}

// ---------------- small kernels ----------------
__global__ void init_kernel() {
    int i = threadIdx.x;
    if (i < E_NUM) d_counts[i] = 0;
}

__global__ void router_kernel(const float* __restrict__ logits,
                              const float* __restrict__ scale) {
    int t = blockIdx.x * blockDim.x + threadIdx.x;
    if (t >= T_TOK) return;
    float l[E_NUM];
#pragma unroll
    for (int e = 0; e < E_NUM; e++) l[e] = logits[t * E_NUM + e];
    int e0 = 0; float v0 = l[0];
#pragma unroll
    for (int e = 1; e < E_NUM; e++) if (l[e] > v0) { v0 = l[e]; e0 = e; }
    int e1 = -1; float v1 = -3.0e38f;
#pragma unroll
    for (int e = 0; e < E_NUM; e++) if (e != e0 && l[e] > v1) { v1 = l[e]; e1 = e; }
    float p1 = expf(v1 - v0);
    float inv = 1.0f / (1.0f + p1);
    d_w[t * 2 + 0] = inv * scale[e0];
    d_w[t * 2 + 1] = p1 * inv * scale[e1];
    d_slot[t * 2 + 0] = e0;
    d_slot[t * 2 + 1] = e1;
    atomicAdd(&d_counts[e0], 1);
    atomicAdd(&d_counts[e1], 1);
}

__global__ void scan_kernel() {
    if (threadIdx.x == 0) {
        int acc = 0;
        for (int e = 0; e < E_NUM; e++) {
            d_off[e] = acc;
            d_pos[e] = acc;
            acc += d_counts[e];
        }
        d_off[E_NUM] = acc;
    }
}

__global__ void scatter_kernel() {
    int t = blockIdx.x * blockDim.x + threadIdx.x;
    if (t >= T_TOK) return;
#pragma unroll
    for (int k = 0; k < K_TOP; k++) {
        int e = d_slot[t * 2 + k];
        int p = atomicAdd(&d_pos[e], 1);
        d_a_tok[p] = t;
        d_slot[t * 2 + k] = p;
    }
}

// ---------------- fp32 -> bf16 hi/lo split (4 elems / thread) ----------------
// TARGET selects destination __device__ arrays IN DEVICE CODE (never pass
// __device__ symbols as host-side kernel arguments — on GB300/ATS that reads
// the zero host shadow silently).
template <int TARGET>   // 0: x, 1: w13, 2: w2
__global__ void split_kernel(const float* __restrict__ in, int n4) {
    int i = blockIdx.x * blockDim.x + threadIdx.x;
    if (i >= n4) return;
    __nv_bfloat16* hi = (TARGET == 0) ? d_x_hi : (TARGET == 1) ? d_w13_hi : d_w2_hi;
    __nv_bfloat16* lo = (TARGET == 0) ? d_x_lo : (TARGET == 1) ? d_w13_lo : d_w2_lo;
    float4 v = ((const float4*)in)[i];
    __nv_bfloat16 h0 = __float2bfloat16_rn(v.x);
    __nv_bfloat16 h1 = __float2bfloat16_rn(v.y);
    __nv_bfloat16 h2 = __float2bfloat16_rn(v.z);
    __nv_bfloat16 h3 = __float2bfloat16_rn(v.w);
    __nv_bfloat16 l0 = __float2bfloat16_rn(v.x - __bfloat162float(h0));
    __nv_bfloat16 l1 = __float2bfloat16_rn(v.y - __bfloat162float(h1));
    __nv_bfloat16 l2 = __float2bfloat16_rn(v.z - __bfloat162float(h2));
    __nv_bfloat16 l3 = __float2bfloat16_rn(v.w - __bfloat162float(h3));
    ((__nv_bfloat162*)hi)[i * 2 + 0] = __nv_bfloat162(h0, h1);
    ((__nv_bfloat162*)hi)[i * 2 + 1] = __nv_bfloat162(h2, h3);
    ((__nv_bfloat162*)lo)[i * 2 + 0] = __nv_bfloat162(l0, l1);
    ((__nv_bfloat162*)lo)[i * 2 + 1] = __nv_bfloat162(l2, l3);
}

// ---------------- activation: h = gelu(g)*u, split to bf16 hi/lo -------------
__global__ void act_kernel() {
    int i = blockIdx.x * blockDim.x + threadIdx.x;       // over NSLOT*I/4
    int n4 = NSLOT * I_DIM / 4;
    if (i >= n4) return;
    int per_row = I_DIM / 4;
    int slot = i / per_row;
    int c4 = i - slot * per_row;
    const float* gp = d_gu + (size_t)slot * (2 * I_DIM) + c4 * 4;
    const float* up = gp + I_DIM;
    float4 g = *(const float4*)gp;
    float4 u = *(const float4*)up;
    float h[4];
    h[0] = 0.5f * g.x * (1.0f + erff(g.x * 0.70710678118654752f)) * u.x;
    h[1] = 0.5f * g.y * (1.0f + erff(g.y * 0.70710678118654752f)) * u.y;
    h[2] = 0.5f * g.z * (1.0f + erff(g.z * 0.70710678118654752f)) * u.z;
    h[3] = 0.5f * g.w * (1.0f + erff(g.w * 0.70710678118654752f)) * u.w;
    __nv_bfloat16 hh[4], hl[4];
#pragma unroll
    for (int q = 0; q < 4; q++) {
        hh[q] = __float2bfloat16_rn(h[q]);
        hl[q] = __float2bfloat16_rn(h[q] - __bfloat162float(hh[q]));
    }
    size_t base2 = (size_t)slot * (I_DIM / 2) + c4 * 2;
    ((__nv_bfloat162*)d_h_hi)[base2 + 0] = __nv_bfloat162(hh[0], hh[1]);
    ((__nv_bfloat162*)d_h_hi)[base2 + 1] = __nv_bfloat162(hh[2], hh[3]);
    ((__nv_bfloat162*)d_h_lo)[base2 + 0] = __nv_bfloat162(hl[0], hl[1]);
    ((__nv_bfloat162*)d_h_lo)[base2 + 1] = __nv_bfloat162(hl[2], hl[3]);
}

// ---------------- grouped GEMM: bf16x2-split 3-mma, fp32 accumulate ----------
// C = A[M,K] * B[N,K]^T with A ~ Ahi+Alo, B ~ Bhi+Blo (bf16 each).
// acc += AhBh + AhBl + AlBh.  K = 1024 in 32 chunks of 32.
// 128x128 CTA tile, 8 warps (2m x 4n), warp tile 64x32, m16n8k16 mma.
// MODE selects operand arrays in device code.
#define SROW 40                      // smem row stride in bf16 (80 B, 8B aligned)
#define BUFB (128 * SROW * 2)        // 10240 bytes per buffer
#define STGB (4 * BUFB)              // 40960 bytes per stage (Ahi,Alo,Bhi,Blo)

template <int MODE>
__global__ __launch_bounds__(256, 2)
void gemm_tc_kernel() {
    constexpr int KD = 1024;
    constexpr int NC = 32;
    constexpr int BROWS = (MODE == 0) ? (2 * I_DIM) : H_DIM;
    constexpr int CSTR  = (MODE == 0) ? (2 * I_DIM) : H_DIM;

    const __nv_bfloat16* __restrict__ Ahi = (MODE == 0) ? d_x_hi  : d_h_hi;
    const __nv_bfloat16* __restrict__ Alo = (MODE == 0) ? d_x_lo  : d_h_lo;
    const __nv_bfloat16* __restrict__ Bhi = (MODE == 0) ? d_w13_hi : d_w2_hi;
    const __nv_bfloat16* __restrict__ Blo = (MODE == 0) ? d_w13_lo : d_w2_lo;

    extern __shared__ char smc[];
    const uint32_t sbase = smem_u32(smc);

    const int tid = threadIdx.x;
    const int wid = tid >> 5;
    const int lane = tid & 31;
    const int g  = lane >> 2;     // 0..7
    const int tg = lane & 3;      // 0..3
    const int warp_m = wid >> 2;  // 0..1
    const int warp_n = wid & 3;   // 0..3

    const int e = blockIdx.z;
    const int m_begin = d_off[e];
    const int m_count = d_off[e + 1] - m_begin;
    const int tile_m = blockIdx.y * 128;
    if (tile_m >= m_count) return;
    const int n0 = blockIdx.x * 128;

    // -------- cp.async mapping: 4 ids/thread, each = (row, 8B-chunk) ---------
    // row has 32 bf16 = 64 B = 8 chunks of 8 B (4 bf16 each)
    const __nv_bfloat16 *pah[4], *pal[4], *pbh[4], *pbl[4];
    uint32_t soff[4];
#pragma unroll
    for (int i = 0; i < 4; i++) {
        int id = tid + i * 256;        // 0..1023
        int row = id >> 3;             // 0..127
        int c = id & 7;                // 8B chunk
        int mrow = tile_m + row;
        int gslot = m_begin + ((mrow < m_count) ? mrow : 0);
        int arow = (MODE == 0) ? d_a_tok[gslot] : gslot;
        pah[i] = Ahi + (size_t)arow * KD + c * 4;
        pal[i] = Alo + (size_t)arow * KD + c * 4;
        size_t brow = (size_t)e * BROWS + n0 + row;
        pbh[i] = Bhi + brow * KD + c * 4;
        pbl[i] = Blo + brow * KD + c * 4;
        soff[i] = (uint32_t)(row * (SROW * 2) + c * 8);
    }

    float acc[4][4][4];
#pragma unroll
    for (int ms = 0; ms < 4; ms++)
#pragma unroll
        for (int ns = 0; ns < 4; ns++)
#pragma unroll
            for (int q = 0; q < 4; q++) acc[ms][ns][q] = 0.0f;

    // prologue: chunk 0 -> stage 0
#pragma unroll
    for (int i = 0; i < 4; i++) {
        CP_ASYNC8(sbase + 0 * BUFB + soff[i], pah[i]);
        CP_ASYNC8(sbase + 1 * BUFB + soff[i], pal[i]);
        CP_ASYNC8(sbase + 2 * BUFB + soff[i], pbh[i]);
        CP_ASYNC8(sbase + 3 * BUFB + soff[i], pbl[i]);
    }
    CP_COMMIT();

    for (int c = 0; c < NC; c++) {
        if (c + 1 < NC) {
            uint32_t st = ((c + 1) & 1) * (uint32_t)STGB;
            int koff = (c + 1) * 32;
#pragma unroll
            for (int i = 0; i < 4; i++) {
                CP_ASYNC8(sbase + st + 0 * BUFB + soff[i], pah[i] + koff);
                CP_ASYNC8(sbase + st + 1 * BUFB + soff[i], pal[i] + koff);
                CP_ASYNC8(sbase + st + 2 * BUFB + soff[i], pbh[i] + koff);
                CP_ASYNC8(sbase + st + 3 * BUFB + soff[i], pbl[i] + koff);
            }
            CP_COMMIT();
            CP_WAIT1();
        } else {
            CP_WAIT0();
        }
        __syncthreads();

        const uint32_t* Ah = (const uint32_t*)(smc + (c & 1) * STGB);
        const uint32_t* Al = Ah + BUFB / 4;
        const uint32_t* Bh = Ah + 2 * (BUFB / 4);
        const uint32_t* Bl = Ah + 3 * (BUFB / 4);

#pragma unroll
        for (int ks = 0; ks < 2; ks++) {        // two k16 steps per 32-chunk
            const int kb = ks * 8;              // word offset in row (20 words/row)
            uint32_t ah[4][4], al[4][4];
#pragma unroll
            for (int ms = 0; ms < 4; ms++) {
                int rb = warp_m * 64 + ms * 16;
                int w0 = (rb + g) * 20 + kb + tg;
                int w1 = (rb + 8 + g) * 20 + kb + tg;
                ah[ms][0] = Ah[w0];     ah[ms][1] = Ah[w1];
                ah[ms][2] = Ah[w0 + 4]; ah[ms][3] = Ah[w1 + 4];
                al[ms][0] = Al[w0];     al[ms][1] = Al[w1];
                al[ms][2] = Al[w0 + 4]; al[ms][3] = Al[w1 + 4];
            }
#pragma unroll
            for (int ns = 0; ns < 4; ns++) {
                int cb = warp_n * 32 + ns * 8;
                int wb = (cb + g) * 20 + kb + tg;
                uint32_t bh[2], bl[2];
                bh[0] = Bh[wb]; bh[1] = Bh[wb + 4];
                bl[0] = Bl[wb]; bl[1] = Bl[wb + 4];
#pragma unroll
                for (int ms = 0; ms < 4; ms++) {
                    mma_bf16(acc[ms][ns], ah[ms], bh);
                    mma_bf16(acc[ms][ns], ah[ms], bl);
                    mma_bf16(acc[ms][ns], al[ms], bh);
                }
            }
        }
        __syncthreads();
    }

    // -------- epilogue --------
    float* Cbase = (MODE == 0) ? d_gu : d_y;
#pragma unroll
    for (int ms = 0; ms < 4; ms++) {
        int r0 = tile_m + warp_m * 64 + ms * 16 + g;
        int r1 = r0 + 8;
#pragma unroll
        for (int ns = 0; ns < 4; ns++) {
            int col = n0 + warp_n * 32 + ns * 8 + 2 * tg;
            if (r0 < m_count) {
                float* p = Cbase + (size_t)(m_begin + r0) * CSTR + col;
                p[0] = acc[ms][ns][0];
                p[1] = acc[ms][ns][1];
            }
            if (r1 < m_count) {
                float* p = Cbase + (size_t)(m_begin + r1) * CSTR + col;
                p[0] = acc[ms][ns][2];
                p[1] = acc[ms][ns][3];
            }
        }
    }
}

// ---------------- combine ----------------
__global__ void combine_kernel(float* __restrict__ out) {
    int idx = blockIdx.x * blockDim.x + threadIdx.x;
    int nvec = T_TOK * H_DIM / 4;
    if (idx >= nvec) return;
    int vecs_per_row = H_DIM / 4;
    int t = idx / vecs_per_row;
    int c = (idx - t * vecs_per_row) * 4;
    float w0 = d_w[t * 2 + 0];
    float w1 = d_w[t * 2 + 1];
    int s0 = d_slot[t * 2 + 0];
    int s1 = d_slot[t * 2 + 1];
    float4 y0 = *(const float4*)(d_y + (size_t)s0 * H_DIM + c);
    float4 y1 = *(const float4*)(d_y + (size_t)s1 * H_DIM + c);
    float4 o;
    o.x = w0 * y0.x + w1 * y1.x;
    o.y = w0 * y0.y + w1 * y1.y;
    o.z = w0 * y0.z + w1 * y1.z;
    o.w = w0 * y0.w + w1 * y1.w;
    *(float4*)(out + (size_t)t * H_DIM + c) = o;
}

// ---------------- launch ----------------
extern "C" void kernel_launch(void* const* d_in, const int* in_sizes, int n_in,
                              void* d_out, int out_size) {
    const float* x      = (const float*)d_in[0];
    const float* logits = (const float*)d_in[1];
    const float* scale  = (const float*)d_in[2];
    const float* w13    = (const float*)d_in[3];
    const float* w2     = (const float*)d_in[4];
    float* out = (float*)d_out;

    const int SMEM = 2 * STGB;   // 81920 bytes
    cudaFuncSetAttribute(gemm_tc_kernel<0>, cudaFuncAttributeMaxDynamicSharedMemorySize, SMEM);
    cudaFuncSetAttribute(gemm_tc_kernel<1>, cudaFuncAttributeMaxDynamicSharedMemorySize, SMEM);

    init_kernel<<<1, 32>>>();
    router_kernel<<<T_TOK / 256, 256>>>(logits, scale);
    scan_kernel<<<1, 32>>>();
    scatter_kernel<<<T_TOK / 256, 256>>>();

    // fp32 -> bf16 hi/lo splits (src pointers are real device pointers from d_in)
    {
        int n4 = T_TOK * H_DIM / 4;
        split_kernel<0><<<(n4 + 255) / 256, 256>>>(x, n4);
    }
    {
        int n4 = E_NUM * 2 * I_DIM * H_DIM / 4;
        split_kernel<1><<<(n4 + 255) / 256, 256>>>(w13, n4);
    }
    {
        int n4 = E_NUM * H_DIM * I_DIM / 4;
        split_kernel<2><<<(n4 + 255) / 256, 256>>>(w2, n4);
    }

    // GEMM1: N = 2*I = 2048 -> 16 n-tiles
    gemm_tc_kernel<0><<<dim3(16, 32, E_NUM), 256, SMEM>>>();

    // GELU * u + split h to bf16 hi/lo
    {
        int n4 = NSLOT * I_DIM / 4;
        act_kernel<<<(n4 + 255) / 256, 256>>>();
    }

    // GEMM2: N = H = 1024 -> 8 n-tiles
    gemm_tc_kernel<1><<<dim3(8, 32, E_NUM), 256, SMEM>>>();

    {
        int nvec = T_TOK * H_DIM / 4;
        combine_kernel<<<(nvec + 255) / 256, 256>>>(out);
    }
}

// round 9
// speedup vs baseline: 3.1920x; 1.4028x over previous
#include <cuda_runtime.h>
#include <cuda_fp16.h>
#include <cstdint>
#include <math.h>

// Problem constants (fixed by the dataset)
#define T_TOK 4096
#define H_DIM 1024
#define E_NUM 8
#define I_DIM 1024
#define K_TOP 2
#define NSLOT (T_TOK * K_TOP)   // 8192 (token,expert) assignments

// ---------------- device scratch ----------------
__device__ int   d_counts[E_NUM];
__device__ int   d_off[E_NUM + 1];
__device__ int   d_pos[E_NUM];
__device__ int   d_a_tok[NSLOT];
__device__ float d_w[NSLOT];
__device__ int   d_slot[NSLOT];
__device__ float d_gu[(size_t)NSLOT * 2 * I_DIM];      // g|u pre-activation (fp32)
__device__ float d_y[(size_t)NSLOT * H_DIM];           // down-proj per slot (fp32)

// fp16 operands: A-side split hi/lo (exact), B-side quantized only
__device__ __half d_x_hi[(size_t)T_TOK * H_DIM];
__device__ __half d_x_lo[(size_t)T_TOK * H_DIM];
__device__ __half d_h_hi[(size_t)NSLOT * I_DIM];
__device__ __half d_h_lo[(size_t)NSLOT * I_DIM];
__device__ __half d_w13_h[(size_t)E_NUM * 2 * I_DIM * H_DIM];
__device__ __half d_w2_h[(size_t)E_NUM * H_DIM * I_DIM];

// ---------------- PTX helpers ----------------
__device__ __forceinline__ uint32_t smem_u32(const void* p) {
    uint32_t a;
    asm("{ .reg .u64 t; cvta.to.shared.u64 t, %1; cvt.u32.u64 %0, t; }" : "=r"(a) : "l"(p));
    return a;
}
#define CP_ASYNC16(dst_u32, src_ptr) \
    asm volatile("cp.async.cg.shared.global [%0], [%1], 16;" :: "r"(dst_u32), "l"(src_ptr))
#define CP_COMMIT() asm volatile("cp.async.commit_group;" ::: "memory")
#define CP_WAIT1()  asm volatile("cp.async.wait_group 1;" ::: "memory")
#define CP_WAIT0()  asm volatile("cp.async.wait_group 0;" ::: "memory")

__device__ __forceinline__ void mma_f16(float* d, const uint32_t* a, const uint32_t* b) {
    asm volatile(
        "mma.sync.aligned.m16n8k16.row.col.f32.f16.f16.f32 "
        "{%0,%1,%2,%3}, {%4,%5,%6,%7}, {%8,%9}, {%0,%1,%2,%3};"
        : "+f"(d[0]), "+f"(d[1]), "+f"(d[2]), "+f"(d[3])
        : "r"(a[0]), "r"(a[1]), "r"(a[2]), "r"(a[3]), "r"(b[0]), "r"(b[1]));
}

// ---------------- small kernels ----------------
__global__ void init_kernel() {
    int i = threadIdx.x;
    if (i < E_NUM) d_counts[i] = 0;
}

__global__ void router_kernel(const float* __restrict__ logits,
                              const float* __restrict__ scale) {
    int t = blockIdx.x * blockDim.x + threadIdx.x;
    if (t >= T_TOK) return;
    float l[E_NUM];
#pragma unroll
    for (int e = 0; e < E_NUM; e++) l[e] = logits[t * E_NUM + e];
    int e0 = 0; float v0 = l[0];
#pragma unroll
    for (int e = 1; e < E_NUM; e++) if (l[e] > v0) { v0 = l[e]; e0 = e; }
    int e1 = -1; float v1 = -3.0e38f;
#pragma unroll
    for (int e = 0; e < E_NUM; e++) if (e != e0 && l[e] > v1) { v1 = l[e]; e1 = e; }
    float p1 = expf(v1 - v0);
    float inv = 1.0f / (1.0f + p1);
    d_w[t * 2 + 0] = inv * scale[e0];
    d_w[t * 2 + 1] = p1 * inv * scale[e1];
    d_slot[t * 2 + 0] = e0;
    d_slot[t * 2 + 1] = e1;
    atomicAdd(&d_counts[e0], 1);
    atomicAdd(&d_counts[e1], 1);
}

__global__ void scan_kernel() {
    if (threadIdx.x == 0) {
        int acc = 0;
        for (int e = 0; e < E_NUM; e++) {
            d_off[e] = acc;
            d_pos[e] = acc;
            acc += d_counts[e];
        }
        d_off[E_NUM] = acc;
    }
}

__global__ void scatter_kernel() {
    int t = blockIdx.x * blockDim.x + threadIdx.x;
    if (t >= T_TOK) return;
#pragma unroll
    for (int k = 0; k < K_TOP; k++) {
        int e = d_slot[t * 2 + k];
        int p = atomicAdd(&d_pos[e], 1);
        d_a_tok[p] = t;
        d_slot[t * 2 + k] = p;
    }
}

// ---------------- fp32 -> fp16 hi/lo exact split (A-side: x) ----------------
__global__ void split_x_kernel(const float* __restrict__ in, int n4) {
    int i = blockIdx.x * blockDim.x + threadIdx.x;
    if (i >= n4) return;
    float4 v = ((const float4*)in)[i];
    __half h0 = __float2half_rn(v.x), h1 = __float2half_rn(v.y);
    __half h2 = __float2half_rn(v.z), h3 = __float2half_rn(v.w);
    __half l0 = __float2half_rn(v.x - __half2float(h0));
    __half l1 = __float2half_rn(v.y - __half2float(h1));
    __half l2 = __float2half_rn(v.z - __half2float(h2));
    __half l3 = __float2half_rn(v.w - __half2float(h3));
    ((half2*)d_x_hi)[i * 2 + 0] = half2(h0, h1);
    ((half2*)d_x_hi)[i * 2 + 1] = half2(h2, h3);
    ((half2*)d_x_lo)[i * 2 + 0] = half2(l0, l1);
    ((half2*)d_x_lo)[i * 2 + 1] = half2(l2, l3);
}

// ---------------- fp32 -> fp16 quantize (B-side: weights) ----------------
template <int TARGET>   // 0: w13, 1: w2
__global__ void quant_w_kernel(const float* __restrict__ in, int n4) {
    int i = blockIdx.x * blockDim.x + threadIdx.x;
    if (i >= n4) return;
    __half* dst = (TARGET == 0) ? d_w13_h : d_w2_h;
    float4 v = ((const float4*)in)[i];
    ((half2*)dst)[i * 2 + 0] = half2(__float2half_rn(v.x), __float2half_rn(v.y));
    ((half2*)dst)[i * 2 + 1] = half2(__float2half_rn(v.z), __float2half_rn(v.w));
}

// ---------------- activation: h = gelu(g)*u, split to fp16 hi/lo -------------
__global__ void act_kernel() {
    int i = blockIdx.x * blockDim.x + threadIdx.x;       // over NSLOT*I/4
    int n4 = NSLOT * I_DIM / 4;
    if (i >= n4) return;
    int per_row = I_DIM / 4;
    int slot = i / per_row;
    int c4 = i - slot * per_row;
    const float* gp = d_gu + (size_t)slot * (2 * I_DIM) + c4 * 4;
    const float* up = gp + I_DIM;
    float4 g = *(const float4*)gp;
    float4 u = *(const float4*)up;
    float h[4];
    h[0] = 0.5f * g.x * (1.0f + erff(g.x * 0.70710678118654752f)) * u.x;
    h[1] = 0.5f * g.y * (1.0f + erff(g.y * 0.70710678118654752f)) * u.y;
    h[2] = 0.5f * g.z * (1.0f + erff(g.z * 0.70710678118654752f)) * u.z;
    h[3] = 0.5f * g.w * (1.0f + erff(g.w * 0.70710678118654752f)) * u.w;
    __half hh[4], hl[4];
#pragma unroll
    for (int q = 0; q < 4; q++) {
        hh[q] = __float2half_rn(h[q]);
        hl[q] = __float2half_rn(h[q] - __half2float(hh[q]));
    }
    size_t base2 = (size_t)slot * (I_DIM / 2) + c4 * 2;
    ((half2*)d_h_hi)[base2 + 0] = half2(hh[0], hh[1]);
    ((half2*)d_h_hi)[base2 + 1] = half2(hh[2], hh[3]);
    ((half2*)d_h_lo)[base2 + 0] = half2(hl[0], hl[1]);
    ((half2*)d_h_lo)[base2 + 1] = half2(hl[2], hl[3]);
}

// ---------------- grouped GEMM: fp16 A-split 2-mma, fp32 accumulate ----------
// C = A[M,K] * B[N,K]^T with A = Ahi + Alo (exact fp16 split), B = rn_fp16(B).
// acc += Ahi*Bh + Alo*Bh = A * Bh.  K = 1024 in 32 chunks of 32.
// CTA: 128 threads, 4 warps (2m x 2n), CTA tile 128x128, warp tile 64x64.
// 3-stage cp.async pipeline (16B ops), one __syncthreads per chunk.
#define SROW 40                      // smem row stride in halves (80 B, 16B-mult)
#define BUFB (128 * SROW * 2)        // 10240 bytes per buffer
#define STGB (3 * BUFB)              // 30720 bytes per stage (Ahi, Alo, Bh)
#define NSTG 3

template <int MODE>
__global__ __launch_bounds__(128, 2)
void gemm_tc_kernel() {
    constexpr int KD = 1024;
    constexpr int NC = 32;
    constexpr int BROWS = (MODE == 0) ? (2 * I_DIM) : H_DIM;
    constexpr int CSTR  = (MODE == 0) ? (2 * I_DIM) : H_DIM;

    const __half* __restrict__ Ahi = (MODE == 0) ? d_x_hi  : d_h_hi;
    const __half* __restrict__ Alo = (MODE == 0) ? d_x_lo  : d_h_lo;
    const __half* __restrict__ Bh  = (MODE == 0) ? d_w13_h : d_w2_h;

    extern __shared__ char smc[];
    const uint32_t sbase = smem_u32(smc);

    const int tid = threadIdx.x;
    const int wid = tid >> 5;
    const int lane = tid & 31;
    const int g  = lane >> 2;     // 0..7
    const int tg = lane & 3;      // 0..3
    const int warp_m = wid >> 1;  // 0..1
    const int warp_n = wid & 1;   // 0..1

    const int e = blockIdx.z;
    const int m_begin = d_off[e];
    const int m_count = d_off[e + 1] - m_begin;
    const int tile_m = blockIdx.y * 128;
    if (tile_m >= m_count) return;
    const int n0 = blockIdx.x * 128;

    // -------- cp.async mapping: 4 ids/thread, each = (row, 16B-chunk) --------
    // row has 32 fp16 = 64 B = 4 chunks of 16 B
    const __half *pah[4], *pal[4], *pbh[4];
    uint32_t soff[4];
#pragma unroll
    for (int i = 0; i < 4; i++) {
        int id = tid + i * 128;        // 0..511
        int row = id >> 2;             // 0..127
        int c = id & 3;                // 16B chunk
        int mrow = tile_m + row;
        int gslot = m_begin + ((mrow < m_count) ? mrow : 0);
        int arow = (MODE == 0) ? d_a_tok[gslot] : gslot;
        pah[i] = Ahi + (size_t)arow * KD + c * 8;
        pal[i] = Alo + (size_t)arow * KD + c * 8;
        size_t brow = (size_t)e * BROWS + n0 + row;
        pbh[i] = Bh + brow * KD + c * 8;
        soff[i] = (uint32_t)(row * (SROW * 2) + c * 16);
    }

    float acc[4][8][4];
#pragma unroll
    for (int ms = 0; ms < 4; ms++)
#pragma unroll
        for (int ns = 0; ns < 8; ns++)
#pragma unroll
            for (int q = 0; q < 4; q++) acc[ms][ns][q] = 0.0f;

    // prologue: issue chunks 0 and 1
#pragma unroll
    for (int cc = 0; cc < 2; cc++) {
        uint32_t st = sbase + cc * STGB;
        int koff = cc * 32;
#pragma unroll
        for (int i = 0; i < 4; i++) {
            CP_ASYNC16(st + 0 * BUFB + soff[i], pah[i] + koff);
            CP_ASYNC16(st + 1 * BUFB + soff[i], pal[i] + koff);
            CP_ASYNC16(st + 2 * BUFB + soff[i], pbh[i] + koff);
        }
        CP_COMMIT();
    }

    for (int c = 0; c < NC; c++) {
        if (c + 1 < NC) CP_WAIT1(); else CP_WAIT0();
        __syncthreads();   // all warps done with stage (c+2)%3 from iteration c-1

        if (c + 2 < NC) {
            int cc = c + 2;
            uint32_t st = sbase + (cc % NSTG) * STGB;
            int koff = cc * 32;
#pragma unroll
            for (int i = 0; i < 4; i++) {
                CP_ASYNC16(st + 0 * BUFB + soff[i], pah[i] + koff);
                CP_ASYNC16(st + 1 * BUFB + soff[i], pal[i] + koff);
                CP_ASYNC16(st + 2 * BUFB + soff[i], pbh[i] + koff);
            }
            CP_COMMIT();
        }

        const uint32_t* A0 = (const uint32_t*)(smc + (c % NSTG) * STGB);
        const uint32_t* A1 = A0 + BUFB / 4;
        const uint32_t* B0 = A0 + 2 * (BUFB / 4);

#pragma unroll
        for (int ks = 0; ks < 2; ks++) {        // two k16 steps per 32-chunk
            const int kb = ks * 8;              // word offset in 20-word row
            uint32_t ah[4][4], al[4][4];
#pragma unroll
            for (int ms = 0; ms < 4; ms++) {
                int rb = warp_m * 64 + ms * 16;
                int w0 = (rb + g) * 20 + kb + tg;
                int w1 = (rb + 8 + g) * 20 + kb + tg;
                ah[ms][0] = A0[w0];     ah[ms][1] = A0[w1];
                ah[ms][2] = A0[w0 + 4]; ah[ms][3] = A0[w1 + 4];
                al[ms][0] = A1[w0];     al[ms][1] = A1[w1];
                al[ms][2] = A1[w0 + 4]; al[ms][3] = A1[w1 + 4];
            }
#pragma unroll
            for (int ns = 0; ns < 8; ns++) {
                int cb = warp_n * 64 + ns * 8;
                int wb = (cb + g) * 20 + kb + tg;
                uint32_t bh[2];
                bh[0] = B0[wb]; bh[1] = B0[wb + 4];
#pragma unroll
                for (int ms = 0; ms < 4; ms++) {
                    mma_f16(acc[ms][ns], ah[ms], bh);
                    mma_f16(acc[ms][ns], al[ms], bh);
                }
            }
        }
    }

    // -------- epilogue --------
    float* Cbase = (MODE == 0) ? d_gu : d_y;
#pragma unroll
    for (int ms = 0; ms < 4; ms++) {
        int r0 = tile_m + warp_m * 64 + ms * 16 + g;
        int r1 = r0 + 8;
#pragma unroll
        for (int ns = 0; ns < 8; ns++) {
            int col = n0 + warp_n * 64 + ns * 8 + 2 * tg;
            if (r0 < m_count) {
                float* p = Cbase + (size_t)(m_begin + r0) * CSTR + col;
                p[0] = acc[ms][ns][0];
                p[1] = acc[ms][ns][1];
            }
            if (r1 < m_count) {
                float* p = Cbase + (size_t)(m_begin + r1) * CSTR + col;
                p[0] = acc[ms][ns][2];
                p[1] = acc[ms][ns][3];
            }
        }
    }
}

// ---------------- combine ----------------
__global__ void combine_kernel(float* __restrict__ out) {
    int idx = blockIdx.x * blockDim.x + threadIdx.x;
    int nvec = T_TOK * H_DIM / 4;
    if (idx >= nvec) return;
    int vecs_per_row = H_DIM / 4;
    int t = idx / vecs_per_row;
    int c = (idx - t * vecs_per_row) * 4;
    float w0 = d_w[t * 2 + 0];
    float w1 = d_w[t * 2 + 1];
    int s0 = d_slot[t * 2 + 0];
    int s1 = d_slot[t * 2 + 1];
    float4 y0 = *(const float4*)(d_y + (size_t)s0 * H_DIM + c);
    float4 y1 = *(const float4*)(d_y + (size_t)s1 * H_DIM + c);
    float4 o;
    o.x = w0 * y0.x + w1 * y1.x;
    o.y = w0 * y0.y + w1 * y1.y;
    o.z = w0 * y0.z + w1 * y1.z;
    o.w = w0 * y0.w + w1 * y1.w;
    *(float4*)(out + (size_t)t * H_DIM + c) = o;
}

// ---------------- launch ----------------
extern "C" void kernel_launch(void* const* d_in, const int* in_sizes, int n_in,
                              void* d_out, int out_size) {
    const float* x      = (const float*)d_in[0];
    const float* logits = (const float*)d_in[1];
    const float* scale  = (const float*)d_in[2];
    const float* w13    = (const float*)d_in[3];
    const float* w2     = (const float*)d_in[4];
    float* out = (float*)d_out;

    const int SMEM = NSTG * STGB;   // 92160 bytes
    cudaFuncSetAttribute(gemm_tc_kernel<0>, cudaFuncAttributeMaxDynamicSharedMemorySize, SMEM);
    cudaFuncSetAttribute(gemm_tc_kernel<1>, cudaFuncAttributeMaxDynamicSharedMemorySize, SMEM);

    init_kernel<<<1, 32>>>();
    router_kernel<<<T_TOK / 256, 256>>>(logits, scale);
    scan_kernel<<<1, 32>>>();
    scatter_kernel<<<T_TOK / 256, 256>>>();

    // operand preparation
    {
        int n4 = T_TOK * H_DIM / 4;
        split_x_kernel<<<(n4 + 255) / 256, 256>>>(x, n4);
    }
    {
        int n4 = E_NUM * 2 * I_DIM * H_DIM / 4;
        quant_w_kernel<0><<<(n4 + 255) / 256, 256>>>(w13, n4);
    }
    {
        int n4 = E_NUM * H_DIM * I_DIM / 4;
        quant_w_kernel<1><<<(n4 + 255) / 256, 256>>>(w2, n4);
    }

    // GEMM1: N = 2*I = 2048 -> 16 n-tiles
    gemm_tc_kernel<0><<<dim3(16, 32, E_NUM), 128, SMEM>>>();

    // GELU * u + split h to fp16 hi/lo
    {
        int n4 = NSLOT * I_DIM / 4;
        act_kernel<<<(n4 + 255) / 256, 256>>>();
    }

    // GEMM2: N = H = 1024 -> 8 n-tiles
    gemm_tc_kernel<1><<<dim3(8, 32, E_NUM), 128, SMEM>>>();

    {
        int nvec = T_TOK * H_DIM / 4;
        combine_kernel<<<(nvec + 255) / 256, 256>>>(out);
    }
}

// round 12
// speedup vs baseline: 5.1055x; 1.5995x over previous
#include <cuda_runtime.h>
#include <cuda_fp16.h>
#include <cstdint>
#include <math.h>

// Problem constants (fixed by the dataset)
#define T_TOK 4096
#define H_DIM 1024
#define E_NUM 8
#define I_DIM 1024
#define K_TOP 2
#define NSLOT (T_TOK * K_TOP)   // 8192 (token,expert) assignments

// ---------------- device scratch ----------------
__device__ int   d_counts[E_NUM];
__device__ int   d_off[E_NUM + 1];
__device__ int   d_pos[E_NUM];
__device__ int   d_a_tok[NSLOT];
__device__ float d_w[NSLOT];
__device__ int   d_slot[NSLOT];
__device__ float d_gu[(size_t)NSLOT * 2 * I_DIM];      // g|u pre-activation (fp32)
__device__ float d_y[(size_t)NSLOT * H_DIM];           // down-proj per slot (fp32)

// fp16 quantized operands
__device__ __half d_x_h[(size_t)T_TOK * H_DIM];
__device__ __half d_h_h[(size_t)NSLOT * I_DIM];
__device__ __half d_w13_h[(size_t)E_NUM * 2 * I_DIM * H_DIM];
__device__ __half d_w2_h[(size_t)E_NUM * H_DIM * I_DIM];

// ---------------- PTX helpers ----------------
__device__ __forceinline__ uint32_t smem_u32(const void* p) {
    uint32_t a;
    asm("{ .reg .u64 t; cvta.to.shared.u64 t, %1; cvt.u32.u64 %0, t; }" : "=r"(a) : "l"(p));
    return a;
}
#define CP_ASYNC16(dst_u32, src_ptr) \
    asm volatile("cp.async.cg.shared.global [%0], [%1], 16;" :: "r"(dst_u32), "l"(src_ptr))
#define CP_COMMIT() asm volatile("cp.async.commit_group;" ::: "memory")
#define CP_WAIT1()  asm volatile("cp.async.wait_group 1;" ::: "memory")
#define CP_WAIT0()  asm volatile("cp.async.wait_group 0;" ::: "memory")

__device__ __forceinline__ void mma_f16(float* d, const uint32_t* a, const uint32_t* b) {
    asm volatile(
        "mma.sync.aligned.m16n8k16.row.col.f32.f16.f16.f32 "
        "{%0,%1,%2,%3}, {%4,%5,%6,%7}, {%8,%9}, {%0,%1,%2,%3};"
        : "+f"(d[0]), "+f"(d[1]), "+f"(d[2]), "+f"(d[3])
        : "r"(a[0]), "r"(a[1]), "r"(a[2]), "r"(a[3]), "r"(b[0]), "r"(b[1]));
}

// ---------------- small kernels ----------------
__global__ void init_kernel() {
    int i = threadIdx.x;
    if (i < E_NUM) d_counts[i] = 0;
}

__global__ void router_kernel(const float* __restrict__ logits,
                              const float* __restrict__ scale) {
    int t = blockIdx.x * blockDim.x + threadIdx.x;
    if (t >= T_TOK) return;
    float l[E_NUM];
#pragma unroll
    for (int e = 0; e < E_NUM; e++) l[e] = logits[t * E_NUM + e];
    int e0 = 0; float v0 = l[0];
#pragma unroll
    for (int e = 1; e < E_NUM; e++) if (l[e] > v0) { v0 = l[e]; e0 = e; }
    int e1 = -1; float v1 = -3.0e38f;
#pragma unroll
    for (int e = 0; e < E_NUM; e++) if (e != e0 && l[e] > v1) { v1 = l[e]; e1 = e; }
    float p1 = expf(v1 - v0);
    float inv = 1.0f / (1.0f + p1);
    d_w[t * 2 + 0] = inv * scale[e0];
    d_w[t * 2 + 1] = p1 * inv * scale[e1];
    d_slot[t * 2 + 0] = e0;
    d_slot[t * 2 + 1] = e1;
    atomicAdd(&d_counts[e0], 1);
    atomicAdd(&d_counts[e1], 1);
}

__global__ void scan_kernel() {
    if (threadIdx.x == 0) {
        int acc = 0;
        for (int e = 0; e < E_NUM; e++) {
            d_off[e] = acc;
            d_pos[e] = acc;
            acc += d_counts[e];
        }
        d_off[E_NUM] = acc;
    }
}

__global__ void scatter_kernel() {
    int t = blockIdx.x * blockDim.x + threadIdx.x;
    if (t >= T_TOK) return;
#pragma unroll
    for (int k = 0; k < K_TOP; k++) {
        int e = d_slot[t * 2 + k];
        int p = atomicAdd(&d_pos[e], 1);
        d_a_tok[p] = t;
        d_slot[t * 2 + k] = p;
    }
}

// ---------------- fp32 -> fp16 quantize (selects dst in device code) ---------
template <int TARGET>   // 0: x, 1: w13, 2: w2
__global__ void quant_kernel(const float* __restrict__ in, int n4) {
    int i = blockIdx.x * blockDim.x + threadIdx.x;
    if (i >= n4) return;
    __half* dst = (TARGET == 0) ? d_x_h : (TARGET == 1) ? d_w13_h : d_w2_h;
    float4 v = ((const float4*)in)[i];
    ((half2*)dst)[i * 2 + 0] = half2(__float2half_rn(v.x), __float2half_rn(v.y));
    ((half2*)dst)[i * 2 + 1] = half2(__float2half_rn(v.z), __float2half_rn(v.w));
}

// ---------------- activation: h = gelu(g)*u -> fp16 --------------------------
__global__ void act_kernel() {
    int i = blockIdx.x * blockDim.x + threadIdx.x;       // over NSLOT*I/4
    int n4 = NSLOT * I_DIM / 4;
    if (i >= n4) return;
    int per_row = I_DIM / 4;
    int slot = i / per_row;
    int c4 = i - slot * per_row;
    const float* gp = d_gu + (size_t)slot * (2 * I_DIM) + c4 * 4;
    const float* up = gp + I_DIM;
    float4 g = *(const float4*)gp;
    float4 u = *(const float4*)up;
    float h[4];
    h[0] = 0.5f * g.x * (1.0f + erff(g.x * 0.70710678118654752f)) * u.x;
    h[1] = 0.5f * g.y * (1.0f + erff(g.y * 0.70710678118654752f)) * u.y;
    h[2] = 0.5f * g.z * (1.0f + erff(g.z * 0.70710678118654752f)) * u.z;
    h[3] = 0.5f * g.w * (1.0f + erff(g.w * 0.70710678118654752f)) * u.w;
    size_t base2 = (size_t)slot * (I_DIM / 2) + c4 * 2;
    ((half2*)d_h_h)[base2 + 0] = half2(__float2half_rn(h[0]), __float2half_rn(h[1]));
    ((half2*)d_h_h)[base2 + 1] = half2(__float2half_rn(h[2]), __float2half_rn(h[3]));
}

// ---------------- grouped GEMM: fp16 single-mma, fp32 accumulate -------------
// C = rn16(A)[M,K] * rn16(B)[N,K]^T.  K = 1024 in 32 chunks of 32.
// CTA: 128 threads, 4 warps (2m x 2n), CTA tile 128x128, warp tile 64x64.
// 3-stage cp.async pipeline (16B ops), one __syncthreads per chunk.
#define SROW 40                      // smem row stride in halves (80 B, 16B-mult)
#define BUFB (128 * SROW * 2)        // 10240 bytes per buffer
#define STGB (2 * BUFB)              // 20480 bytes per stage (A, B)
#define NSTG 3

template <int MODE>
__global__ __launch_bounds__(128, 2)
void gemm_tc_kernel() {
    constexpr int KD = 1024;
    constexpr int NC = 32;
    constexpr int BROWS = (MODE == 0) ? (2 * I_DIM) : H_DIM;
    constexpr int CSTR  = (MODE == 0) ? (2 * I_DIM) : H_DIM;

    const __half* __restrict__ Ah = (MODE == 0) ? d_x_h   : d_h_h;
    const __half* __restrict__ Bh = (MODE == 0) ? d_w13_h : d_w2_h;

    extern __shared__ char smc[];
    const uint32_t sbase = smem_u32(smc);

    const int tid = threadIdx.x;
    const int wid = tid >> 5;
    const int lane = tid & 31;
    const int g  = lane >> 2;     // 0..7
    const int tg = lane & 3;      // 0..3
    const int warp_m = wid >> 1;  // 0..1
    const int warp_n = wid & 1;   // 0..1

    const int e = blockIdx.z;
    const int m_begin = d_off[e];
    const int m_count = d_off[e + 1] - m_begin;
    const int tile_m = blockIdx.y * 128;
    if (tile_m >= m_count) return;
    const int n0 = blockIdx.x * 128;

    // -------- cp.async mapping: 4 ids/thread, each = (row, 16B-chunk) --------
    // row has 32 fp16 = 64 B = 4 chunks of 16 B
    const __half *pa[4], *pb[4];
    uint32_t soff[4];
#pragma unroll
    for (int i = 0; i < 4; i++) {
        int id = tid + i * 128;        // 0..511
        int row = id >> 2;             // 0..127
        int c = id & 3;                // 16B chunk
        int mrow = tile_m + row;
        int gslot = m_begin + ((mrow < m_count) ? mrow : 0);
        int arow = (MODE == 0) ? d_a_tok[gslot] : gslot;
        pa[i] = Ah + (size_t)arow * KD + c * 8;
        size_t brow = (size_t)e * BROWS + n0 + row;
        pb[i] = Bh + brow * KD + c * 8;
        soff[i] = (uint32_t)(row * (SROW * 2) + c * 16);
    }

    float acc[4][8][4];
#pragma unroll
    for (int ms = 0; ms < 4; ms++)
#pragma unroll
        for (int ns = 0; ns < 8; ns++)
#pragma unroll
            for (int q = 0; q < 4; q++) acc[ms][ns][q] = 0.0f;

    // prologue: issue chunks 0 and 1
#pragma unroll
    for (int cc = 0; cc < 2; cc++) {
        uint32_t st = sbase + cc * STGB;
        int koff = cc * 32;
#pragma unroll
        for (int i = 0; i < 4; i++) {
            CP_ASYNC16(st + 0 * BUFB + soff[i], pa[i] + koff);
            CP_ASYNC16(st + 1 * BUFB + soff[i], pb[i] + koff);
        }
        CP_COMMIT();
    }

    for (int c = 0; c < NC; c++) {
        if (c + 1 < NC) CP_WAIT1(); else CP_WAIT0();
        __syncthreads();   // all warps done with stage (c+2)%3 from iteration c-1

        if (c + 2 < NC) {
            int cc = c + 2;
            uint32_t st = sbase + (cc % NSTG) * STGB;
            int koff = cc * 32;
#pragma unroll
            for (int i = 0; i < 4; i++) {
                CP_ASYNC16(st + 0 * BUFB + soff[i], pa[i] + koff);
                CP_ASYNC16(st + 1 * BUFB + soff[i], pb[i] + koff);
            }
            CP_COMMIT();
        }

        const uint32_t* A0 = (const uint32_t*)(smc + (c % NSTG) * STGB);
        const uint32_t* B0 = A0 + BUFB / 4;

#pragma unroll
        for (int ks = 0; ks < 2; ks++) {        // two k16 steps per 32-chunk
            const int kb = ks * 8;              // word offset in 20-word row
            uint32_t af[4][4];
#pragma unroll
            for (int ms = 0; ms < 4; ms++) {
                int rb = warp_m * 64 + ms * 16;
                int w0 = (rb + g) * 20 + kb + tg;
                int w1 = (rb + 8 + g) * 20 + kb + tg;
                af[ms][0] = A0[w0];     af[ms][1] = A0[w1];
                af[ms][2] = A0[w0 + 4]; af[ms][3] = A0[w1 + 4];
            }
#pragma unroll
            for (int ns = 0; ns < 8; ns++) {
                int cb = warp_n * 64 + ns * 8;
                int wb = (cb + g) * 20 + kb + tg;
                uint32_t bf[2];
                bf[0] = B0[wb]; bf[1] = B0[wb + 4];
#pragma unroll
                for (int ms = 0; ms < 4; ms++)
                    mma_f16(acc[ms][ns], af[ms], bf);
            }
        }
    }

    // -------- epilogue --------
    float* Cbase = (MODE == 0) ? d_gu : d_y;
#pragma unroll
    for (int ms = 0; ms < 4; ms++) {
        int r0 = tile_m + warp_m * 64 + ms * 16 + g;
        int r1 = r0 + 8;
#pragma unroll
        for (int ns = 0; ns < 8; ns++) {
            int col = n0 + warp_n * 64 + ns * 8 + 2 * tg;
            if (r0 < m_count) {
                float* p = Cbase + (size_t)(m_begin + r0) * CSTR + col;
                p[0] = acc[ms][ns][0];
                p[1] = acc[ms][ns][1];
            }
            if (r1 < m_count) {
                float* p = Cbase + (size_t)(m_begin + r1) * CSTR + col;
                p[0] = acc[ms][ns][2];
                p[1] = acc[ms][ns][3];
            }
        }
    }
}

// ---------------- combine ----------------
__global__ void combine_kernel(float* __restrict__ out) {
    int idx = blockIdx.x * blockDim.x + threadIdx.x;
    int nvec = T_TOK * H_DIM / 4;
    if (idx >= nvec) return;
    int vecs_per_row = H_DIM / 4;
    int t = idx / vecs_per_row;
    int c = (idx - t * vecs_per_row) * 4;
    float w0 = d_w[t * 2 + 0];
    float w1 = d_w[t * 2 + 1];
    int s0 = d_slot[t * 2 + 0];
    int s1 = d_slot[t * 2 + 1];
    float4 y0 = *(const float4*)(d_y + (size_t)s0 * H_DIM + c);
    float4 y1 = *(const float4*)(d_y + (size_t)s1 * H_DIM + c);
    float4 o;
    o.x = w0 * y0.x + w1 * y1.x;
    o.y = w0 * y0.y + w1 * y1.y;
    o.z = w0 * y0.z + w1 * y1.z;
    o.w = w0 * y0.w + w1 * y1.w;
    *(float4*)(out + (size_t)t * H_DIM + c) = o;
}

// ---------------- launch ----------------
extern "C" void kernel_launch(void* const* d_in, const int* in_sizes, int n_in,
                              void* d_out, int out_size) {
    const float* x      = (const float*)d_in[0];
    const float* logits = (const float*)d_in[1];
    const float* scale  = (const float*)d_in[2];
    const float* w13    = (const float*)d_in[3];
    const float* w2     = (const float*)d_in[4];
    float* out = (float*)d_out;

    const int SMEM = NSTG * STGB;   // 61440 bytes
    cudaFuncSetAttribute(gemm_tc_kernel<0>, cudaFuncAttributeMaxDynamicSharedMemorySize, SMEM);
    cudaFuncSetAttribute(gemm_tc_kernel<1>, cudaFuncAttributeMaxDynamicSharedMemorySize, SMEM);

    init_kernel<<<1, 32>>>();
    router_kernel<<<T_TOK / 256, 256>>>(logits, scale);
    scan_kernel<<<1, 32>>>();
    scatter_kernel<<<T_TOK / 256, 256>>>();

    // operand quantization
    {
        int n4 = T_TOK * H_DIM / 4;
        quant_kernel<0><<<(n4 + 255) / 256, 256>>>(x, n4);
    }
    {
        int n4 = E_NUM * 2 * I_DIM * H_DIM / 4;
        quant_kernel<1><<<(n4 + 255) / 256, 256>>>(w13, n4);
    }
    {
        int n4 = E_NUM * H_DIM * I_DIM / 4;
        quant_kernel<2><<<(n4 + 255) / 256, 256>>>(w2, n4);
    }

    // GEMM1: N = 2*I = 2048 -> 16 n-tiles
    gemm_tc_kernel<0><<<dim3(16, 32, E_NUM), 128, SMEM>>>();

    // GELU * u -> fp16 h
    {
        int n4 = NSLOT * I_DIM / 4;
        act_kernel<<<(n4 + 255) / 256, 256>>>();
    }

    // GEMM2: N = H = 1024 -> 8 n-tiles
    gemm_tc_kernel<1><<<dim3(8, 32, E_NUM), 128, SMEM>>>();

    {
        int nvec = T_TOK * H_DIM / 4;
        combine_kernel<<<(nvec + 255) / 256, 256>>>(out);
    }
}

// round 13
// speedup vs baseline: 5.4626x; 1.0699x over previous
#include <cuda_runtime.h>
#include <cuda_fp16.h>
#include <cstdint>
#include <math.h>

// Problem constants (fixed by the dataset)
#define T_TOK 4096
#define H_DIM 1024
#define E_NUM 8
#define I_DIM 1024
#define K_TOP 2
#define NSLOT (T_TOK * K_TOP)   // 8192 (token,expert) assignments

// ---------------- device scratch ----------------
__device__ int   d_counts[E_NUM];
__device__ int   d_off[E_NUM + 1];
__device__ int   d_pos[E_NUM];
__device__ int   d_a_tok[NSLOT];
__device__ float d_w[NSLOT];
__device__ int   d_slot[NSLOT];
__device__ float d_wslot[NSLOT];               // slot -> combine weight

// fp16 quantized operands
__device__ __half d_x_h[(size_t)T_TOK * H_DIM];
__device__ __half d_h_h[(size_t)NSLOT * I_DIM];
__device__ __half d_w13_h[(size_t)E_NUM * 2 * I_DIM * H_DIM];
__device__ __half d_w2_h[(size_t)E_NUM * H_DIM * I_DIM];

// ---------------- PTX helpers ----------------
__device__ __forceinline__ uint32_t smem_u32(const void* p) {
    uint32_t a;
    asm("{ .reg .u64 t; cvta.to.shared.u64 t, %1; cvt.u32.u64 %0, t; }" : "=r"(a) : "l"(p));
    return a;
}
#define CP_ASYNC16(dst_u32, src_ptr) \
    asm volatile("cp.async.cg.shared.global [%0], [%1], 16;" :: "r"(dst_u32), "l"(src_ptr))
#define CP_COMMIT() asm volatile("cp.async.commit_group;" ::: "memory")
#define CP_WAIT1()  asm volatile("cp.async.wait_group 1;" ::: "memory")
#define CP_WAIT0()  asm volatile("cp.async.wait_group 0;" ::: "memory")

__device__ __forceinline__ void mma_f16(float* d, const uint32_t* a, const uint32_t* b) {
    asm volatile(
        "mma.sync.aligned.m16n8k16.row.col.f32.f16.f16.f32 "
        "{%0,%1,%2,%3}, {%4,%5,%6,%7}, {%8,%9}, {%0,%1,%2,%3};"
        : "+f"(d[0]), "+f"(d[1]), "+f"(d[2]), "+f"(d[3])
        : "r"(a[0]), "r"(a[1]), "r"(a[2]), "r"(a[3]), "r"(b[0]), "r"(b[1]));
}

__device__ __forceinline__ float gelu_f(float g) {
    return 0.5f * g * (1.0f + erff(g * 0.70710678118654752f));
}

// ---------------- small kernels ----------------
__global__ void init_kernel() {
    int i = threadIdx.x;
    if (i < E_NUM) d_counts[i] = 0;
}

__global__ void router_kernel(const float* __restrict__ logits,
                              const float* __restrict__ scale) {
    int t = blockIdx.x * blockDim.x + threadIdx.x;
    if (t >= T_TOK) return;
    float l[E_NUM];
#pragma unroll
    for (int e = 0; e < E_NUM; e++) l[e] = logits[t * E_NUM + e];
    int e0 = 0; float v0 = l[0];
#pragma unroll
    for (int e = 1; e < E_NUM; e++) if (l[e] > v0) { v0 = l[e]; e0 = e; }
    int e1 = -1; float v1 = -3.0e38f;
#pragma unroll
    for (int e = 0; e < E_NUM; e++) if (e != e0 && l[e] > v1) { v1 = l[e]; e1 = e; }
    float p1 = expf(v1 - v0);
    float inv = 1.0f / (1.0f + p1);
    d_w[t * 2 + 0] = inv * scale[e0];
    d_w[t * 2 + 1] = p1 * inv * scale[e1];
    d_slot[t * 2 + 0] = e0;
    d_slot[t * 2 + 1] = e1;
    atomicAdd(&d_counts[e0], 1);
    atomicAdd(&d_counts[e1], 1);
}

__global__ void scan_kernel() {
    if (threadIdx.x == 0) {
        int acc = 0;
        for (int e = 0; e < E_NUM; e++) {
            d_off[e] = acc;
            d_pos[e] = acc;
            acc += d_counts[e];
        }
        d_off[E_NUM] = acc;
    }
}

__global__ void scatter_kernel() {
    int t = blockIdx.x * blockDim.x + threadIdx.x;
    if (t >= T_TOK) return;
#pragma unroll
    for (int k = 0; k < K_TOP; k++) {
        int e = d_slot[t * 2 + k];
        int p = atomicAdd(&d_pos[e], 1);
        d_a_tok[p] = t;
        d_wslot[p] = d_w[t * 2 + k];
        d_slot[t * 2 + k] = p;
    }
}

// ---------------- fp32 -> fp16 quantize (selects dst in device code) ---------
template <int TARGET>   // 0: x, 1: w13, 2: w2
__global__ void quant_kernel(const float* __restrict__ in, int n4) {
    int i = blockIdx.x * blockDim.x + threadIdx.x;
    if (i >= n4) return;
    __half* dst = (TARGET == 0) ? d_x_h : (TARGET == 1) ? d_w13_h : d_w2_h;
    float4 v = ((const float4*)in)[i];
    ((half2*)dst)[i * 2 + 0] = half2(__float2half_rn(v.x), __float2half_rn(v.y));
    ((half2*)dst)[i * 2 + 1] = half2(__float2half_rn(v.z), __float2half_rn(v.w));
}

// ---------------- zero output ----------------
__global__ void zero_out_kernel(float* __restrict__ out) {
    int i = blockIdx.x * blockDim.x + threadIdx.x;
    if (i < T_TOK * H_DIM / 4)
        ((float4*)out)[i] = make_float4(0.f, 0.f, 0.f, 0.f);
}

// ---------------- grouped GEMM: fp16 single-mma, fp32 accumulate -------------
// MODE 0 (gemm1 + fused GELU): each CTA covers 64 h-columns. The 128-row B tile
//   interleaves w1/w3 at 8-row granularity: smem B row r -> source row
//   e*2048 + ((r>>3)&1)*1024 + n0 + (r>>4)*8 + (r&7).  In-thread acc slice
//   ns=2q holds g, ns=2q+1 holds u for the SAME output (row, h-col) ->
//   epilogue writes d_h_h = gelu(g)*u directly (fp16).
// MODE 1 (gemm2 + fused combine): epilogue atomicAdds w_slot * acc into
//   out[token, col].
// CTA: 128 threads, 4 warps (2m x 2n), CTA tile 128x128, warp tile 64x64.
// 3-stage cp.async pipeline (16B ops), one __syncthreads per chunk.
#define SROW 40                      // smem row stride in halves (80 B, 16B-mult)
#define BUFB (128 * SROW * 2)        // 10240 bytes per buffer
#define STGB (2 * BUFB)              // 20480 bytes per stage (A, B)
#define NSTG 3

template <int MODE>
__global__ __launch_bounds__(128, 2)
void gemm_tc_kernel(float* __restrict__ out) {
    constexpr int KD = 1024;
    constexpr int NC = 32;

    const __half* __restrict__ Ah = (MODE == 0) ? d_x_h   : d_h_h;
    const __half* __restrict__ Bh = (MODE == 0) ? d_w13_h : d_w2_h;

    extern __shared__ char smc[];
    const uint32_t sbase = smem_u32(smc);

    const int tid = threadIdx.x;
    const int wid = tid >> 5;
    const int lane = tid & 31;
    const int g  = lane >> 2;     // 0..7
    const int tg = lane & 3;      // 0..3
    const int warp_m = wid >> 1;  // 0..1
    const int warp_n = wid & 1;   // 0..1

    const int e = blockIdx.z;
    const int m_begin = d_off[e];
    const int m_count = d_off[e + 1] - m_begin;
    const int tile_m = blockIdx.y * 128;
    if (tile_m >= m_count) return;
    // MODE 0: n0 = base h-column (64 per CTA). MODE 1: n0 = base out-column.
    const int n0 = blockIdx.x * ((MODE == 0) ? 64 : 128);

    // -------- cp.async mapping: 4 ids/thread, each = (row, 16B-chunk) --------
    const __half *pa[4], *pb[4];
    uint32_t soff[4];
#pragma unroll
    for (int i = 0; i < 4; i++) {
        int id = tid + i * 128;        // 0..511
        int row = id >> 2;             // 0..127
        int c = id & 3;                // 16B chunk
        int mrow = tile_m + row;
        int gslot = m_begin + ((mrow < m_count) ? mrow : 0);
        int arow = (MODE == 0) ? d_a_tok[gslot] : gslot;
        pa[i] = Ah + (size_t)arow * KD + c * 8;
        size_t brow;
        if (MODE == 0) {
            int sub = (row >> 3) & 1;          // 0: w1, 1: w3
            brow = (size_t)e * (2 * I_DIM) + (size_t)sub * I_DIM
                 + n0 + (row >> 4) * 8 + (row & 7);
        } else {
            brow = (size_t)e * H_DIM + n0 + row;
        }
        pb[i] = Bh + brow * KD + c * 8;
        soff[i] = (uint32_t)(row * (SROW * 2) + c * 16);
    }

    float acc[4][8][4];
#pragma unroll
    for (int ms = 0; ms < 4; ms++)
#pragma unroll
        for (int ns = 0; ns < 8; ns++)
#pragma unroll
            for (int q = 0; q < 4; q++) acc[ms][ns][q] = 0.0f;

    // prologue: issue chunks 0 and 1
#pragma unroll
    for (int cc = 0; cc < 2; cc++) {
        uint32_t st = sbase + cc * STGB;
        int koff = cc * 32;
#pragma unroll
        for (int i = 0; i < 4; i++) {
            CP_ASYNC16(st + 0 * BUFB + soff[i], pa[i] + koff);
            CP_ASYNC16(st + 1 * BUFB + soff[i], pb[i] + koff);
        }
        CP_COMMIT();
    }

    for (int c = 0; c < NC; c++) {
        if (c + 1 < NC) CP_WAIT1(); else CP_WAIT0();
        __syncthreads();   // all warps done with stage (c+2)%3 from iteration c-1

        if (c + 2 < NC) {
            int cc = c + 2;
            uint32_t st = sbase + (cc % NSTG) * STGB;
            int koff = cc * 32;
#pragma unroll
            for (int i = 0; i < 4; i++) {
                CP_ASYNC16(st + 0 * BUFB + soff[i], pa[i] + koff);
                CP_ASYNC16(st + 1 * BUFB + soff[i], pb[i] + koff);
            }
            CP_COMMIT();
        }

        const uint32_t* A0 = (const uint32_t*)(smc + (c % NSTG) * STGB);
        const uint32_t* B0 = A0 + BUFB / 4;

#pragma unroll
        for (int ks = 0; ks < 2; ks++) {        // two k16 steps per 32-chunk
            const int kb = ks * 8;              // word offset in 20-word row
            uint32_t af[4][4];
#pragma unroll
            for (int ms = 0; ms < 4; ms++) {
                int rb = warp_m * 64 + ms * 16;
                int w0 = (rb + g) * 20 + kb + tg;
                int w1 = (rb + 8 + g) * 20 + kb + tg;
                af[ms][0] = A0[w0];     af[ms][1] = A0[w1];
                af[ms][2] = A0[w0 + 4]; af[ms][3] = A0[w1 + 4];
            }
#pragma unroll
            for (int ns = 0; ns < 8; ns++) {
                int cb = warp_n * 64 + ns * 8;
                int wb = (cb + g) * 20 + kb + tg;
                uint32_t bf[2];
                bf[0] = B0[wb]; bf[1] = B0[wb + 4];
#pragma unroll
                for (int ms = 0; ms < 4; ms++)
                    mma_f16(acc[ms][ns], af[ms], bf);
            }
        }
    }

    // -------- epilogue --------
    if (MODE == 0) {
        // acc[ms][2q] = g, acc[ms][2q+1] = u for h-col hb = n0+(warp_n*4+q)*8+2tg
#pragma unroll
        for (int ms = 0; ms < 4; ms++) {
            int r0 = tile_m + warp_m * 64 + ms * 16 + g;
            int r1 = r0 + 8;
#pragma unroll
            for (int q = 0; q < 4; q++) {
                int col = n0 + (warp_n * 4 + q) * 8 + 2 * tg;
                float* gv = acc[ms][2 * q];
                float* uv = acc[ms][2 * q + 1];
                if (r0 < m_count) {
                    float h0 = gelu_f(gv[0]) * uv[0];
                    float h1 = gelu_f(gv[1]) * uv[1];
                    *(half2*)(d_h_h + (size_t)(m_begin + r0) * I_DIM + col) =
                        half2(__float2half_rn(h0), __float2half_rn(h1));
                }
                if (r1 < m_count) {
                    float h2 = gelu_f(gv[2]) * uv[2];
                    float h3 = gelu_f(gv[3]) * uv[3];
                    *(half2*)(d_h_h + (size_t)(m_begin + r1) * I_DIM + col) =
                        half2(__float2half_rn(h2), __float2half_rn(h3));
                }
            }
        }
    } else {
        // fused combine: out[tok, col] += w_slot * acc
#pragma unroll
        for (int ms = 0; ms < 4; ms++) {
            int r0 = tile_m + warp_m * 64 + ms * 16 + g;
            int r1 = r0 + 8;
            int t0 = 0, t1 = 0;
            float ws0 = 0.f, ws1 = 0.f;
            if (r0 < m_count) { t0 = d_a_tok[m_begin + r0]; ws0 = d_wslot[m_begin + r0]; }
            if (r1 < m_count) { t1 = d_a_tok[m_begin + r1]; ws1 = d_wslot[m_begin + r1]; }
#pragma unroll
            for (int ns = 0; ns < 8; ns++) {
                int col = n0 + warp_n * 64 + ns * 8 + 2 * tg;
                if (r0 < m_count) {
                    float* p = out + (size_t)t0 * H_DIM + col;
                    atomicAdd(p + 0, ws0 * acc[ms][ns][0]);
                    atomicAdd(p + 1, ws0 * acc[ms][ns][1]);
                }
                if (r1 < m_count) {
                    float* p = out + (size_t)t1 * H_DIM + col;
                    atomicAdd(p + 0, ws1 * acc[ms][ns][2]);
                    atomicAdd(p + 1, ws1 * acc[ms][ns][3]);
                }
            }
        }
    }
}

// ---------------- launch ----------------
extern "C" void kernel_launch(void* const* d_in, const int* in_sizes, int n_in,
                              void* d_out, int out_size) {
    const float* x      = (const float*)d_in[0];
    const float* logits = (const float*)d_in[1];
    const float* scale  = (const float*)d_in[2];
    const float* w13    = (const float*)d_in[3];
    const float* w2     = (const float*)d_in[4];
    float* out = (float*)d_out;

    const int SMEM = NSTG * STGB;   // 61440 bytes
    cudaFuncSetAttribute(gemm_tc_kernel<0>, cudaFuncAttributeMaxDynamicSharedMemorySize, SMEM);
    cudaFuncSetAttribute(gemm_tc_kernel<1>, cudaFuncAttributeMaxDynamicSharedMemorySize, SMEM);

    init_kernel<<<1, 32>>>();
    router_kernel<<<T_TOK / 256, 256>>>(logits, scale);
    scan_kernel<<<1, 32>>>();
    scatter_kernel<<<T_TOK / 256, 256>>>();

    // operand quantization
    {
        int n4 = T_TOK * H_DIM / 4;
        quant_kernel<0><<<(n4 + 255) / 256, 256>>>(x, n4);
    }
    {
        int n4 = E_NUM * 2 * I_DIM * H_DIM / 4;
        quant_kernel<1><<<(n4 + 255) / 256, 256>>>(w13, n4);
    }
    {
        int n4 = E_NUM * H_DIM * I_DIM / 4;
        quant_kernel<2><<<(n4 + 255) / 256, 256>>>(w2, n4);
    }

    // zero the output (gemm2 accumulates into it)
    zero_out_kernel<<<(T_TOK * H_DIM / 4 + 255) / 256, 256>>>(out);

    // GEMM1 + fused GELU: 16 n-tiles of 64 h-cols each
    gemm_tc_kernel<0><<<dim3(16, 32, E_NUM), 128, SMEM>>>(out);

    // GEMM2 + fused combine: 8 n-tiles of 128 cols
    gemm_tc_kernel<1><<<dim3(8, 32, E_NUM), 128, SMEM>>>(out);
}